// round 3
// baseline (speedup 1.0000x reference)
#include <cuda_runtime.h>
#include <cuda_bf16.h>
#include <cstdint>

// Problem constants (shape fixed by dataset: img [64, 3, 512, 512])
constexpr int NCH = 64 * 3;        // 192 channels
constexpr int P   = 512 * 512;     // 262144 pixels / channel
constexpr int NB  = 256;           // bins

// Scratch (no cudaMalloc allowed) — __device__ globals
__device__ int   g_hist[NCH * NB];
__device__ float g_lut [NCH * NB];
__device__ int   g_step[NCH];

// ---------------------------------------------------------------------------
// Kernel 1: zero the global histogram (must run every launch; graph replays)
// ---------------------------------------------------------------------------
__global__ void zero_hist_kernel() {
    int i = blockIdx.x * blockDim.x + threadIdx.x;
    if (i < NCH * NB) g_hist[i] = 0;
}

// ---------------------------------------------------------------------------
// Kernel 2: per-channel histogram. grid = (BLOCKS_PER_CH, NCH), 256 threads.
// 8 privatized shared sub-histograms to spread same-bin atomics.
// ---------------------------------------------------------------------------
constexpr int HIST_BLOCKS_PER_CH = 32;

__global__ void hist_kernel(const float* __restrict__ in) {
    __shared__ int sh[NB * 8];
    const int c = blockIdx.y;

    for (int i = threadIdx.x; i < NB * 8; i += blockDim.x) sh[i] = 0;
    __syncthreads();

    const float4* base = reinterpret_cast<const float4*>(in + (size_t)c * P);
    const int vec_per_block = (P / 4) / HIST_BLOCKS_PER_CH;   // 2048
    const int start = blockIdx.x * vec_per_block;
    const int sub = threadIdx.x & 7;

    for (int i = threadIdx.x; i < vec_per_block; i += blockDim.x) {
        float4 v = base[start + i];
        atomicAdd(&sh[((int)v.x) * 8 + sub], 1);
        atomicAdd(&sh[((int)v.y) * 8 + sub], 1);
        atomicAdd(&sh[((int)v.z) * 8 + sub], 1);
        atomicAdd(&sh[((int)v.w) * 8 + sub], 1);
    }
    __syncthreads();

    for (int b = threadIdx.x; b < NB; b += blockDim.x) {
        int s = 0;
#pragma unroll
        for (int k = 0; k < 8; k++) s += sh[b * 8 + k];
        atomicAdd(&g_hist[c * NB + b], s);
    }
}

// ---------------------------------------------------------------------------
// Kernel 3: build per-channel LUT. grid = NCH blocks of 256 threads.
// Exact PIL integer math matching the reference:
//   step = (P - last_nonzero_val) / 255   (floor, nonneg)
//   lut[i] = i==0 ? 0 : clamp((cs[i-1] + step/2) / max(step,1), 0, 255)
// ---------------------------------------------------------------------------
__global__ void lut_kernel() {
    const int c = blockIdx.x;
    const int i = threadIdx.x;

    __shared__ int h[NB];
    __shared__ int cs[NB];
    __shared__ int red[NB];

    const int hv = g_hist[c * NB + i];
    h[i]  = hv;
    cs[i] = hv;
    __syncthreads();

    // Inclusive Hillis-Steele scan over 256 elements
#pragma unroll
    for (int off = 1; off < NB; off <<= 1) {
        int v = (i >= off) ? cs[i - off] : 0;
        __syncthreads();
        cs[i] += v;
        __syncthreads();
    }

    // Last nonzero bin index (max-reduce of i where h[i] != 0)
    red[i] = (hv != 0) ? i : -1;
    __syncthreads();
#pragma unroll
    for (int s = 128; s > 0; s >>= 1) {
        if (i < s) red[i] = max(red[i], red[i + s]);
        __syncthreads();
    }
    const int last_idx = red[0];                    // >= 0 always (P > 0)
    const int last_val = h[last_idx];

    const int step = (P - last_val) / 255;
    const int safe = step > 0 ? step : 1;
    if (i == 0) g_step[c] = step;

    const int prev = (i == 0) ? 0 : cs[i - 1];
    int lv = (prev + step / 2) / safe;
    lv = min(max(lv, 0), 255);
    g_lut[c * NB + i] = (float)lv;
}

// ---------------------------------------------------------------------------
// Kernel 4: apply LUT. grid = (BLOCKS_PER_CH, NCH), 256 threads, float4 I/O.
// LUT staged in shared (1 KB). step==0 channels pass through.
// ---------------------------------------------------------------------------
constexpr int APPLY_BLOCKS_PER_CH = 64;

__global__ void apply_kernel(const float* __restrict__ in, float* __restrict__ out) {
    __shared__ float slut[NB];
    __shared__ int sstep;

    const int c = blockIdx.y;
    if (threadIdx.x < NB) slut[threadIdx.x] = g_lut[c * NB + threadIdx.x];
    if (threadIdx.x == 0) sstep = g_step[c];
    __syncthreads();

    const float4* bi = reinterpret_cast<const float4*>(in  + (size_t)c * P);
    float4*       bo = reinterpret_cast<float4*>      (out + (size_t)c * P);
    const int vec_per_block = (P / 4) / APPLY_BLOCKS_PER_CH;  // 1024
    const int start = blockIdx.x * vec_per_block;

    if (sstep == 0) {
        for (int i = threadIdx.x; i < vec_per_block; i += blockDim.x)
            bo[start + i] = bi[start + i];
    } else {
        for (int i = threadIdx.x; i < vec_per_block; i += blockDim.x) {
            float4 v = bi[start + i];
            float4 o;
            o.x = slut[(int)v.x];
            o.y = slut[(int)v.y];
            o.z = slut[(int)v.z];
            o.w = slut[(int)v.w];
            bo[start + i] = o;
        }
    }
}

// ---------------------------------------------------------------------------
extern "C" void kernel_launch(void* const* d_in, const int* in_sizes, int n_in,
                              void* d_out, int out_size) {
    const float* img = (const float*)d_in[0];
    float* out = (float*)d_out;

    zero_hist_kernel<<<(NCH * NB + 255) / 256, 256>>>();
    hist_kernel<<<dim3(HIST_BLOCKS_PER_CH, NCH), 256>>>(img);
    lut_kernel<<<NCH, 256>>>();
    apply_kernel<<<dim3(APPLY_BLOCKS_PER_CH, NCH), 256>>>(img, out);
}